// round 14
// baseline (speedup 1.0000x reference)
#include <cuda_runtime.h>
#include <cuda_bf16.h>
#include <cuda_fp16.h>
#include <cstdint>

#define NTOK 65536
#define DIM  512
#define NEXP 8

// GEMM tile: BM=128 x BN=128, BK=64, 3-stage cp.async, fp16 1-pass,
// 8 warps (2m x 4n), warp tile 64x32, A-fragment double buffering.
#define BM 128
#define BN 128
#define BK 64
#define KSTEPS (DIM / BK)          // 8
#define STAGES 3
#define ROWB 144                   // bytes per smem tile row (64 fp16 + 16B pad)
#define TILE_B (128 * ROWB)        // 18432 : one tile (A or B)
#define BUF_B  (2 * TILE_B)        // 36864 : one stage (A + B)
#define OFF_TOK   0
#define OFF_DST   512
#define OFF_WT    1024
#define OFF_BIAS  1536
#define OFF_TILES 2048
#define GEMM_SMEM (OFF_TILES + STAGES * BUF_B)   // 112640 -> 2 CTAs/SM

// gate v3 config: 256 threads = 256 tokens per block
#define GT_TOK 256

// ---------------- device scratch ----------------
__device__ unsigned  g_cnt[NEXP];
__device__ int       g_tok[NEXP * NTOK];
__device__ float     g_wt [NEXP * NTOK];
__device__ __half    g_xh[(size_t)NTOK * DIM];
__device__ __half    g_wh[(size_t)NEXP * DIM * DIM];
__device__ __half    g_scrh[(size_t)2 * NTOK * DIM];   // fp16 contributions

// ---------------- helpers ----------------
__device__ __forceinline__ uint32_t pkh(__half a, __half b) {
    return (uint32_t)__half_as_ushort(a) | ((uint32_t)__half_as_ushort(b) << 16);
}
__device__ __forceinline__ uint32_t smem_u32(const void* p) {
    return (uint32_t)__cvta_generic_to_shared(p);
}
__device__ __forceinline__ void cpasync16(uint32_t dst, const void* src) {
    asm volatile("cp.async.cg.shared.global [%0], [%1], 16;\n" :: "r"(dst), "l"(src));
}
__device__ __forceinline__ void cp_commit() { asm volatile("cp.async.commit_group;\n" ::: "memory"); }
__device__ __forceinline__ void cp_wait1()  { asm volatile("cp.async.wait_group 1;\n" ::: "memory"); }

__device__ __forceinline__ void ldmx4(uint32_t* r, uint32_t addr) {
    asm volatile("ldmatrix.sync.aligned.m8n8.x4.shared.b16 {%0,%1,%2,%3}, [%4];\n"
                 : "=r"(r[0]), "=r"(r[1]), "=r"(r[2]), "=r"(r[3]) : "r"(addr));
}
__device__ __forceinline__ void mma16816h(float* c, const uint32_t* a, uint32_t b0, uint32_t b1) {
    asm volatile("mma.sync.aligned.m16n8k16.row.col.f32.f16.f16.f32 "
                 "{%0,%1,%2,%3}, {%4,%5,%6,%7}, {%8,%9}, {%0,%1,%2,%3};\n"
                 : "+f"(c[0]), "+f"(c[1]), "+f"(c[2]), "+f"(c[3])
                 : "r"(a[0]), "r"(a[1]), "r"(a[2]), "r"(a[3]), "r"(b0), "r"(b1));
}

// ---------------- kernel 1: W -> fp16 (+ counter reset folded in) ----------------
__global__ void prepw_kernel(const float* __restrict__ W) {
    if (blockIdx.x == 0 && threadIdx.x < NEXP) g_cnt[threadIdx.x] = 0;
    int idx = blockIdx.x * blockDim.x + threadIdx.x;
    float4 v = reinterpret_cast<const float4*>(W)[idx];
    uint2 u;
    u.x = pkh(__float2half_rn(v.x), __float2half_rn(v.y));
    u.y = pkh(__float2half_rn(v.z), __float2half_rn(v.w));
    reinterpret_cast<uint2*>(g_wh)[idx] = u;
}

// ---------------- kernel 2: gate v3 — thread-per-token, broadcast Wg, 256 thr ----------------
__global__ __launch_bounds__(GT_TOK) void gate_kernel(const float* __restrict__ x,
                                                      const float* __restrict__ Wg,
                                                      const float* __restrict__ bg) {
    __shared__ float4 sWg4[NEXP * 128];        // 16 KB
    __shared__ float4 xs4[GT_TOK * 9];         // 36 KB: 8 float4 per token + 1 pad
    const int tid = threadIdx.x;
    const int t0  = blockIdx.x * GT_TOK;

    for (int i = tid; i < NEXP * 128; i += GT_TOK)
        sWg4[i] = reinterpret_cast<const float4*>(Wg)[i];

    float acc[NEXP];
#pragma unroll
    for (int e = 0; e < NEXP; e++) acc[e] = 0.f;

    for (int c = 0; c < 16; c++) {
        __syncthreads();   // xs reuse guard (covers sWg on first pass)
#pragma unroll
        for (int j = 0; j < 8; j++) {
            const int idx = tid + j * GT_TOK;   // 0..2047
            const int row = idx >> 3, k4 = idx & 7;
            float4 v = reinterpret_cast<const float4*>(x)[(size_t)(t0 + row) * 128 + c * 8 + k4];
            xs4[row * 9 + k4] = v;
            uint2 u;
            u.x = pkh(__float2half_rn(v.x), __float2half_rn(v.y));
            u.y = pkh(__float2half_rn(v.z), __float2half_rn(v.w));
            reinterpret_cast<uint2*>(g_xh)[(size_t)(t0 + row) * 128 + c * 8 + k4] = u;
        }
        __syncthreads();
#pragma unroll
        for (int k4 = 0; k4 < 8; k4++) {
            const float4 xv = xs4[tid * 9 + k4];
#pragma unroll
            for (int e = 0; e < NEXP; e++) {
                const float4 wv = sWg4[e * 128 + c * 8 + k4];
                acc[e] += xv.x * wv.x;
                acc[e] += xv.y * wv.y;
                acc[e] += xv.z * wv.z;
                acc[e] += xv.w * wv.w;
            }
        }
    }

    const int t = t0 + tid;
    float v[NEXP];
#pragma unroll
    for (int e = 0; e < NEXP; e++) v[e] = acc[e] + bg[e];
    int e0 = 0;
#pragma unroll
    for (int e = 1; e < NEXP; e++) if (v[e] > v[e0]) e0 = e;   // ties: lower index
    int e1 = (e0 == 0) ? 1 : 0;
#pragma unroll
    for (int e = 0; e < NEXP; e++) if (e != e0 && v[e] > v[e1]) e1 = e;
    float d  = expf(v[e1] - v[e0]);
    float w0 = 1.f / (1.f + d);
    float w1 = 1.f - w0;

    unsigned p0 = atomicAdd(&g_cnt[e0], 1u);
    g_tok[e0 * NTOK + p0] = t;
    g_wt [e0 * NTOK + p0] = w0;
    unsigned p1 = atomicAdd(&g_cnt[e1], 1u);
    g_tok[e1 * NTOK + p1] = t | (1 << 16);
    g_wt [e1 * NTOK + p1] = w1;
}

// ---------------- kernel 3: grouped expert GEMM, fp16, 8 warps x (64x32), BK=64 ----------------
// A-fragment double buffering: next k16's ah ldsm issued under current k16's MMAs.
__global__ __launch_bounds__(256, 2) void moe_gemm_mma(const float* __restrict__ bias) {
    extern __shared__ char smem[];
    const int e = blockIdx.y;
    const unsigned cnt = g_cnt[e];
    const int m0 = blockIdx.x * BM;
    if ((unsigned)m0 >= cnt) return;
    const int valid = min(BM, (int)(cnt - m0));
    const int n0 = blockIdx.z * BN;

    const int tid  = threadIdx.x;
    const int lane = tid & 31, wid = tid >> 5;
    const int warp_m = wid & 1, warp_n = wid >> 1;   // 2m x 4n
    const uint32_t sb = smem_u32(smem);

    int*   s_tok  = reinterpret_cast<int*>(smem + OFF_TOK);
    int*   s_dst  = reinterpret_cast<int*>(smem + OFF_DST);
    float* s_wt   = reinterpret_cast<float*>(smem + OFF_WT);
    float* s_bias = reinterpret_cast<float*>(smem + OFF_BIAS);

    if (tid < 128) {
        int raw = 0; float w = 0.f;
        if (tid < valid) { raw = g_tok[e * NTOK + m0 + tid]; w = g_wt[e * NTOK + m0 + tid]; }
        int t = raw & 0xFFFF;
        s_tok[tid] = t;
        s_dst[tid] = (raw >> 16) * NTOK + t;
        s_wt [tid] = w;
        s_bias[tid] = bias[e * DIM + n0 + tid];
    }
    __syncthreads();

    // ---- loader: each thread owns rows r0+32j (j<4) of A and B, one 16B chunk col
    const int r0 = tid >> 3;          // 0..31
    const int cc = tid & 7;           // 16B chunk within 128B row
    const char* srcA[4];
#pragma unroll
    for (int j = 0; j < 4; j++)
        srcA[j] = reinterpret_cast<const char*>(g_xh + (size_t)s_tok[r0 + 32 * j] * DIM + cc * 8);
    const char* srcB = reinterpret_cast<const char*>(
        g_wh + (size_t)e * DIM * DIM + (size_t)(n0 + r0) * DIM + cc * 8);
    const uint32_t dstA = sb + OFF_TILES + r0 * ROWB + cc * 16;
    const uint32_t dstB = dstA + TILE_B;

    // ---- ldmatrix base addresses (buf 0, k16 = 0); add bufOff + k16*32 at use
    const int aRow = ((lane >> 3) & 1) * 8 + (lane & 7);
    const int aCol = ((lane >> 4) & 1) * 8;
    const int bRow = ((lane >> 4) & 1) * 8 + (lane & 7);
    const int bCol = ((lane >> 3) & 1) * 8;
    uint32_t aAddr[4], bAddr[2];
#pragma unroll
    for (int mt = 0; mt < 4; mt++)
        aAddr[mt] = sb + OFF_TILES + (warp_m * 64 + mt * 16 + aRow) * ROWB + aCol * 2;
#pragma unroll
    for (int pr = 0; pr < 2; pr++)
        bAddr[pr] = sb + OFF_TILES + TILE_B + (warp_n * 32 + pr * 16 + bRow) * ROWB + bCol * 2;

    float acc[4][4][4];
#pragma unroll
    for (int a = 0; a < 4; a++)
#pragma unroll
        for (int b2 = 0; b2 < 4; b2++)
#pragma unroll
            for (int c = 0; c < 4; c++) acc[a][b2][c] = 0.f;

    // ---- prologue: 2 stages in flight
#pragma unroll
    for (int ks = 0; ks < 2; ks++) {
        const uint32_t bo = ks * BUF_B;
        const int off = ks * (BK * 2);      // bytes along K
#pragma unroll
        for (int j = 0; j < 4; j++) cpasync16(dstA + bo + j * 32 * ROWB, srcA[j] + off);
#pragma unroll
        for (int j = 0; j < 4; j++) cpasync16(dstB + bo + j * 32 * ROWB, srcB + off + j * 32 * (DIM * 2));
        cp_commit();
    }

    // ---- mainloop: one barrier per 64-K stage (8 total), ah double-buffered
    uint32_t ah[2][4][4];
    for (int ks = 0; ks < KSTEPS; ks++) {
        cp_wait1();
        __syncthreads();
        if (ks + 2 < KSTEPS) {
            const uint32_t bo = ((ks + 2) % STAGES) * BUF_B;
            const int off = (ks + 2) * (BK * 2);
#pragma unroll
            for (int j = 0; j < 4; j++) cpasync16(dstA + bo + j * 32 * ROWB, srcA[j] + off);
#pragma unroll
            for (int j = 0; j < 4; j++) cpasync16(dstB + bo + j * 32 * ROWB, srcB + off + j * 32 * (DIM * 2));
        }
        cp_commit();

        const uint32_t bufOff = (ks % STAGES) * BUF_B;
        // prime: k16=0 A fragments
#pragma unroll
        for (int mt = 0; mt < 4; mt++) ldmx4(ah[0][mt], aAddr[mt] + bufOff);
#pragma unroll
        for (int k16 = 0; k16 < 4; k16++) {
            const int cur = k16 & 1;
            const uint32_t ko = bufOff + k16 * 32;
            uint32_t bh[2][4];
            ldmx4(bh[0], bAddr[0] + ko);
            ldmx4(bh[1], bAddr[1] + ko);
            if (k16 < 3) {
                const uint32_t kn = bufOff + (k16 + 1) * 32;
#pragma unroll
                for (int mt = 0; mt < 4; mt++) ldmx4(ah[cur ^ 1][mt], aAddr[mt] + kn);
            }
#pragma unroll
            for (int pr = 0; pr < 2; pr++) {
                const int nt = pr * 2;
#pragma unroll
                for (int mt = 0; mt < 4; mt++) {
                    mma16816h(acc[mt][nt],     ah[cur][mt], bh[pr][0], bh[pr][1]);
                    mma16816h(acc[mt][nt + 1], ah[cur][mt], bh[pr][2], bh[pr][3]);
                }
            }
        }
    }

    // ---- epilogue: scr = half( w * (acc + bias) )  (deterministic slot)
    const int g  = lane >> 2;
    const int tg = lane & 3;
#pragma unroll
    for (int mt = 0; mt < 4; mt++) {
        const int rr0 = warp_m * 64 + mt * 16 + g;
        const int rr1 = rr0 + 8;
        const bool ok0 = rr0 < valid, ok1 = rr1 < valid;
        const float w0 = s_wt[rr0], w1 = s_wt[rr1];
        const size_t d0 = (size_t)s_dst[rr0] * DIM;
        const size_t d1 = (size_t)s_dst[rr1] * DIM;
#pragma unroll
        for (int nt = 0; nt < 4; nt++) {
            const int cloc = warp_n * 32 + nt * 8 + tg * 2;
            const int col  = n0 + cloc;
            const float b0v = s_bias[cloc], b1v = s_bias[cloc + 1];
            if (ok0) {
                __half2 h = __floats2half2_rn(w0 * (acc[mt][nt][0] + b0v),
                                              w0 * (acc[mt][nt][1] + b1v));
                *reinterpret_cast<__half2*>(g_scrh + d0 + col) = h;
            }
            if (ok1) {
                __half2 h = __floats2half2_rn(w1 * (acc[mt][nt][2] + b0v),
                                              w1 * (acc[mt][nt][3] + b1v));
                *reinterpret_cast<__half2*>(g_scrh + d1 + col) = h;
            }
        }
    }
}

// ---------------- kernel 4: combine (fp16 scr -> fp32 out) ----------------
__global__ void combine_kernel(float* __restrict__ out) {
    const uint4* s = reinterpret_cast<const uint4*>(g_scrh);   // 8 halves per uint4
    float4* o = reinterpret_cast<float4*>(out);
    const int total = NTOK * (DIM / 8);
    for (int i = blockIdx.x * blockDim.x + threadIdx.x; i < total; i += gridDim.x * blockDim.x) {
        uint4 a = s[i];
        uint4 b = s[i + total];
        const __half2* ah = reinterpret_cast<const __half2*>(&a);
        const __half2* bh = reinterpret_cast<const __half2*>(&b);
        float4 o0, o1;
        float2 p0 = __half22float2(ah[0]), q0 = __half22float2(bh[0]);
        float2 p1 = __half22float2(ah[1]), q1 = __half22float2(bh[1]);
        float2 p2 = __half22float2(ah[2]), q2 = __half22float2(bh[2]);
        float2 p3 = __half22float2(ah[3]), q3 = __half22float2(bh[3]);
        o0.x = p0.x + q0.x; o0.y = p0.y + q0.y;
        o0.z = p1.x + q1.x; o0.w = p1.y + q1.y;
        o1.x = p2.x + q2.x; o1.y = p2.y + q2.y;
        o1.z = p3.x + q3.x; o1.w = p3.y + q3.y;
        o[i * 2]     = o0;
        o[i * 2 + 1] = o1;
    }
}

// ---------------- launch ----------------
extern "C" void kernel_launch(void* const* d_in, const int* in_sizes, int n_in,
                              void* d_out, int out_size) {
    const float* x  = (const float*)d_in[0];
    const float* W  = (const float*)d_in[1];
    const float* b  = (const float*)d_in[2];
    const float* Wg = (const float*)d_in[3];
    const float* bg = (const float*)d_in[4];
    float* out = (float*)d_out;

    cudaFuncSetAttribute(moe_gemm_mma, cudaFuncAttributeMaxDynamicSharedMemorySize, GEMM_SMEM);

    prepw_kernel<<<(NEXP * DIM * DIM / 4) / 256, 256>>>(W);
    gate_kernel<<<NTOK / GT_TOK, GT_TOK>>>(x, Wg, bg);
    dim3 grid(NTOK / BM, NEXP, DIM / BN);   // m fastest (R12 config)
    moe_gemm_mma<<<grid, 256, GEMM_SMEM>>>(b);
    combine_kernel<<<8192, 256>>>(out);
}

// round 15
// speedup vs baseline: 1.0478x; 1.0478x over previous
#include <cuda_runtime.h>
#include <cuda_bf16.h>
#include <cuda_fp16.h>
#include <cstdint>

#define NTOK 65536
#define DIM  512
#define NEXP 8

// GEMM tile: BM=128 x BN=128, BK=64, 3-stage cp.async, fp16 1-pass,
// 8 warps (2m x 4n), warp tile 64x32.  (R12 configuration)
#define BM 128
#define BN 128
#define BK 64
#define KSTEPS (DIM / BK)          // 8
#define STAGES 3
#define ROWB 144                   // bytes per smem tile row (64 fp16 + 16B pad)
#define TILE_B (128 * ROWB)        // 18432 : one tile (A or B)
#define BUF_B  (2 * TILE_B)        // 36864 : one stage (A + B)
#define OFF_TOK   0
#define OFF_DST   512
#define OFF_WT    1024
#define OFF_BIAS  1536
#define OFF_TILES 2048
#define GEMM_SMEM (OFF_TILES + STAGES * BUF_B)   // 112640 -> 2 CTAs/SM

// fused prep+gate config
#define GT_TOK 256                 // tokens per gate block (= threads)
#define PW_BLOCKS 2048             // prepw blocks (E*D*D/4 float4 / 256 thr)
#define GT_BLOCKS (NTOK / GT_TOK)  // 256

// ---------------- device scratch (zero-initialized at module load) ----------------
__device__ unsigned  g_cnt[NEXP];
__device__ int       g_tok[NEXP * NTOK];
__device__ float     g_wt [NEXP * NTOK];
__device__ __half    g_xh[(size_t)NTOK * DIM];
__device__ __half    g_wh[(size_t)NEXP * DIM * DIM];
__device__ __half    g_scrh[(size_t)2 * NTOK * DIM];   // fp16 contributions

// ---------------- helpers ----------------
__device__ __forceinline__ uint32_t pkh(__half a, __half b) {
    return (uint32_t)__half_as_ushort(a) | ((uint32_t)__half_as_ushort(b) << 16);
}
__device__ __forceinline__ uint32_t smem_u32(const void* p) {
    return (uint32_t)__cvta_generic_to_shared(p);
}
__device__ __forceinline__ void cpasync16(uint32_t dst, const void* src) {
    asm volatile("cp.async.cg.shared.global [%0], [%1], 16;\n" :: "r"(dst), "l"(src));
}
__device__ __forceinline__ void cp_commit() { asm volatile("cp.async.commit_group;\n" ::: "memory"); }
__device__ __forceinline__ void cp_wait1()  { asm volatile("cp.async.wait_group 1;\n" ::: "memory"); }

__device__ __forceinline__ void ldmx4(uint32_t* r, uint32_t addr) {
    asm volatile("ldmatrix.sync.aligned.m8n8.x4.shared.b16 {%0,%1,%2,%3}, [%4];\n"
                 : "=r"(r[0]), "=r"(r[1]), "=r"(r[2]), "=r"(r[3]) : "r"(addr));
}
__device__ __forceinline__ void mma16816h(float* c, const uint32_t* a, uint32_t b0, uint32_t b1) {
    asm volatile("mma.sync.aligned.m16n8k16.row.col.f32.f16.f16.f32 "
                 "{%0,%1,%2,%3}, {%4,%5,%6,%7}, {%8,%9}, {%0,%1,%2,%3};\n"
                 : "+f"(c[0]), "+f"(c[1]), "+f"(c[2]), "+f"(c[3])
                 : "r"(a[0]), "r"(a[1]), "r"(a[2]), "r"(a[3]), "r"(b0), "r"(b1));
}

// ---------------- kernel 1: fused prepw + gate ----------------
// blocks [0, PW_BLOCKS)           : W -> fp16
// blocks [PW_BLOCKS, +GT_BLOCKS)  : gate v3 (thread-per-token, broadcast Wg)
// g_cnt is zero at entry: zero-init at load + reset at tail of combine_kernel.
__global__ __launch_bounds__(GT_TOK) void prep_gate_kernel(const float* __restrict__ x,
                                                           const float* __restrict__ W,
                                                           const float* __restrict__ Wg,
                                                           const float* __restrict__ bg) {
    __shared__ float4 sWg4[NEXP * 128];        // 16 KB
    __shared__ float4 xs4[GT_TOK * 9];         // 36 KB: 8 float4 per token + 1 pad
    const int tid = threadIdx.x;

    if (blockIdx.x < PW_BLOCKS) {
        // ---- prepw part: one float4 of W per thread
        const int idx = blockIdx.x * GT_TOK + tid;
        float4 v = reinterpret_cast<const float4*>(W)[idx];
        uint2 u;
        u.x = pkh(__float2half_rn(v.x), __float2half_rn(v.y));
        u.y = pkh(__float2half_rn(v.z), __float2half_rn(v.w));
        reinterpret_cast<uint2*>(g_wh)[idx] = u;
        return;
    }

    // ---- gate part
    const int t0 = (blockIdx.x - PW_BLOCKS) * GT_TOK;

    for (int i = tid; i < NEXP * 128; i += GT_TOK)
        sWg4[i] = reinterpret_cast<const float4*>(Wg)[i];

    float acc[NEXP];
#pragma unroll
    for (int e = 0; e < NEXP; e++) acc[e] = 0.f;

    for (int c = 0; c < 16; c++) {
        __syncthreads();   // xs reuse guard (covers sWg on first pass)
#pragma unroll
        for (int j = 0; j < 8; j++) {
            const int idx = tid + j * GT_TOK;   // 0..2047
            const int row = idx >> 3, k4 = idx & 7;
            float4 v = reinterpret_cast<const float4*>(x)[(size_t)(t0 + row) * 128 + c * 8 + k4];
            xs4[row * 9 + k4] = v;
            uint2 u;
            u.x = pkh(__float2half_rn(v.x), __float2half_rn(v.y));
            u.y = pkh(__float2half_rn(v.z), __float2half_rn(v.w));
            reinterpret_cast<uint2*>(g_xh)[(size_t)(t0 + row) * 128 + c * 8 + k4] = u;
        }
        __syncthreads();
#pragma unroll
        for (int k4 = 0; k4 < 8; k4++) {
            const float4 xv = xs4[tid * 9 + k4];
#pragma unroll
            for (int e = 0; e < NEXP; e++) {
                const float4 wv = sWg4[e * 128 + c * 8 + k4];
                acc[e] += xv.x * wv.x;
                acc[e] += xv.y * wv.y;
                acc[e] += xv.z * wv.z;
                acc[e] += xv.w * wv.w;
            }
        }
    }

    const int t = t0 + tid;
    float v[NEXP];
#pragma unroll
    for (int e = 0; e < NEXP; e++) v[e] = acc[e] + bg[e];
    int e0 = 0;
#pragma unroll
    for (int e = 1; e < NEXP; e++) if (v[e] > v[e0]) e0 = e;   // ties: lower index
    int e1 = (e0 == 0) ? 1 : 0;
#pragma unroll
    for (int e = 0; e < NEXP; e++) if (e != e0 && v[e] > v[e1]) e1 = e;
    float d  = expf(v[e1] - v[e0]);
    float w0 = 1.f / (1.f + d);
    float w1 = 1.f - w0;

    unsigned p0 = atomicAdd(&g_cnt[e0], 1u);
    g_tok[e0 * NTOK + p0] = t;
    g_wt [e0 * NTOK + p0] = w0;
    unsigned p1 = atomicAdd(&g_cnt[e1], 1u);
    g_tok[e1 * NTOK + p1] = t | (1 << 16);
    g_wt [e1 * NTOK + p1] = w1;
}

// ---------------- kernel 2: grouped expert GEMM, fp16, 8 warps x (64x32), BK=64 ----------------
__global__ __launch_bounds__(256, 2) void moe_gemm_mma(const float* __restrict__ bias) {
    extern __shared__ char smem[];
    const int e = blockIdx.y;
    const unsigned cnt = g_cnt[e];
    const int m0 = blockIdx.x * BM;
    if ((unsigned)m0 >= cnt) return;
    const int valid = min(BM, (int)(cnt - m0));
    const int n0 = blockIdx.z * BN;

    const int tid  = threadIdx.x;
    const int lane = tid & 31, wid = tid >> 5;
    const int warp_m = wid & 1, warp_n = wid >> 1;   // 2m x 4n
    const uint32_t sb = smem_u32(smem);

    int*   s_tok  = reinterpret_cast<int*>(smem + OFF_TOK);
    int*   s_dst  = reinterpret_cast<int*>(smem + OFF_DST);
    float* s_wt   = reinterpret_cast<float*>(smem + OFF_WT);
    float* s_bias = reinterpret_cast<float*>(smem + OFF_BIAS);

    if (tid < 128) {
        int raw = 0; float w = 0.f;
        if (tid < valid) { raw = g_tok[e * NTOK + m0 + tid]; w = g_wt[e * NTOK + m0 + tid]; }
        int t = raw & 0xFFFF;
        s_tok[tid] = t;
        s_dst[tid] = (raw >> 16) * NTOK + t;
        s_wt [tid] = w;
        s_bias[tid] = bias[e * DIM + n0 + tid];
    }
    __syncthreads();

    // ---- loader: each thread owns rows r0+32j (j<4) of A and B, one 16B chunk col
    const int r0 = tid >> 3;          // 0..31
    const int cc = tid & 7;           // 16B chunk within 128B row
    const char* srcA[4];
#pragma unroll
    for (int j = 0; j < 4; j++)
        srcA[j] = reinterpret_cast<const char*>(g_xh + (size_t)s_tok[r0 + 32 * j] * DIM + cc * 8);
    const char* srcB = reinterpret_cast<const char*>(
        g_wh + (size_t)e * DIM * DIM + (size_t)(n0 + r0) * DIM + cc * 8);
    const uint32_t dstA = sb + OFF_TILES + r0 * ROWB + cc * 16;
    const uint32_t dstB = dstA + TILE_B;

    // ---- ldmatrix base addresses (buf 0, k16 = 0); add bufOff + k16*32 at use
    const int aRow = ((lane >> 3) & 1) * 8 + (lane & 7);
    const int aCol = ((lane >> 4) & 1) * 8;
    const int bRow = ((lane >> 4) & 1) * 8 + (lane & 7);
    const int bCol = ((lane >> 3) & 1) * 8;
    uint32_t aAddr[4], bAddr[2];
#pragma unroll
    for (int mt = 0; mt < 4; mt++)
        aAddr[mt] = sb + OFF_TILES + (warp_m * 64 + mt * 16 + aRow) * ROWB + aCol * 2;
#pragma unroll
    for (int pr = 0; pr < 2; pr++)
        bAddr[pr] = sb + OFF_TILES + TILE_B + (warp_n * 32 + pr * 16 + bRow) * ROWB + bCol * 2;

    float acc[4][4][4];
#pragma unroll
    for (int a = 0; a < 4; a++)
#pragma unroll
        for (int b2 = 0; b2 < 4; b2++)
#pragma unroll
            for (int c = 0; c < 4; c++) acc[a][b2][c] = 0.f;

    // ---- prologue: 2 stages in flight
#pragma unroll
    for (int ks = 0; ks < 2; ks++) {
        const uint32_t bo = ks * BUF_B;
        const int off = ks * (BK * 2);      // bytes along K
#pragma unroll
        for (int j = 0; j < 4; j++) cpasync16(dstA + bo + j * 32 * ROWB, srcA[j] + off);
#pragma unroll
        for (int j = 0; j < 4; j++) cpasync16(dstB + bo + j * 32 * ROWB, srcB + off + j * 32 * (DIM * 2));
        cp_commit();
    }

    // ---- mainloop: one barrier per 64-K stage (8 total)
    for (int ks = 0; ks < KSTEPS; ks++) {
        cp_wait1();
        __syncthreads();
        if (ks + 2 < KSTEPS) {
            const uint32_t bo = ((ks + 2) % STAGES) * BUF_B;
            const int off = (ks + 2) * (BK * 2);
#pragma unroll
            for (int j = 0; j < 4; j++) cpasync16(dstA + bo + j * 32 * ROWB, srcA[j] + off);
#pragma unroll
            for (int j = 0; j < 4; j++) cpasync16(dstB + bo + j * 32 * ROWB, srcB + off + j * 32 * (DIM * 2));
        }
        cp_commit();

        const uint32_t bufOff = (ks % STAGES) * BUF_B;
#pragma unroll
        for (int k16 = 0; k16 < 4; k16++) {
            const uint32_t ko = bufOff + k16 * 32;
            uint32_t ah[4][4];
#pragma unroll
            for (int mt = 0; mt < 4; mt++) ldmx4(ah[mt], aAddr[mt] + ko);
#pragma unroll
            for (int pr = 0; pr < 2; pr++) {
                uint32_t bh[4];
                ldmx4(bh, bAddr[pr] + ko);
                const int nt = pr * 2;
#pragma unroll
                for (int mt = 0; mt < 4; mt++) {
                    mma16816h(acc[mt][nt],     ah[mt], bh[0], bh[1]);
                    mma16816h(acc[mt][nt + 1], ah[mt], bh[2], bh[3]);
                }
            }
        }
    }

    // ---- epilogue: scr = half( w * (acc + bias) )  (deterministic slot)
    const int g  = lane >> 2;
    const int tg = lane & 3;
#pragma unroll
    for (int mt = 0; mt < 4; mt++) {
        const int rr0 = warp_m * 64 + mt * 16 + g;
        const int rr1 = rr0 + 8;
        const bool ok0 = rr0 < valid, ok1 = rr1 < valid;
        const float w0 = s_wt[rr0], w1 = s_wt[rr1];
        const size_t d0 = (size_t)s_dst[rr0] * DIM;
        const size_t d1 = (size_t)s_dst[rr1] * DIM;
#pragma unroll
        for (int nt = 0; nt < 4; nt++) {
            const int cloc = warp_n * 32 + nt * 8 + tg * 2;
            const int col  = n0 + cloc;
            const float b0v = s_bias[cloc], b1v = s_bias[cloc + 1];
            if (ok0) {
                __half2 h = __floats2half2_rn(w0 * (acc[mt][nt][0] + b0v),
                                              w0 * (acc[mt][nt][1] + b1v));
                *reinterpret_cast<__half2*>(g_scrh + d0 + col) = h;
            }
            if (ok1) {
                __half2 h = __floats2half2_rn(w1 * (acc[mt][nt][2] + b0v),
                                              w1 * (acc[mt][nt][3] + b1v));
                *reinterpret_cast<__half2*>(g_scrh + d1 + col) = h;
            }
        }
    }
}

// ---------------- kernel 3: combine (fp16 scr -> fp32 out) + counter reset for next run ----------------
__global__ void combine_kernel(float* __restrict__ out) {
    if (blockIdx.x == 0 && threadIdx.x < NEXP) g_cnt[threadIdx.x] = 0;  // reset for next replay
    const uint4* s = reinterpret_cast<const uint4*>(g_scrh);   // 8 halves per uint4
    float4* o = reinterpret_cast<float4*>(out);
    const int total = NTOK * (DIM / 8);
    for (int i = blockIdx.x * blockDim.x + threadIdx.x; i < total; i += gridDim.x * blockDim.x) {
        uint4 a = s[i];
        uint4 b = s[i + total];
        const __half2* ah = reinterpret_cast<const __half2*>(&a);
        const __half2* bh = reinterpret_cast<const __half2*>(&b);
        float4 o0, o1;
        float2 p0 = __half22float2(ah[0]), q0 = __half22float2(bh[0]);
        float2 p1 = __half22float2(ah[1]), q1 = __half22float2(bh[1]);
        float2 p2 = __half22float2(ah[2]), q2 = __half22float2(bh[2]);
        float2 p3 = __half22float2(ah[3]), q3 = __half22float2(bh[3]);
        o0.x = p0.x + q0.x; o0.y = p0.y + q0.y;
        o0.z = p1.x + q1.x; o0.w = p1.y + q1.y;
        o1.x = p2.x + q2.x; o1.y = p2.y + q2.y;
        o1.z = p3.x + q3.x; o1.w = p3.y + q3.y;
        o[i * 2]     = o0;
        o[i * 2 + 1] = o1;
    }
}

// ---------------- launch ----------------
extern "C" void kernel_launch(void* const* d_in, const int* in_sizes, int n_in,
                              void* d_out, int out_size) {
    const float* x  = (const float*)d_in[0];
    const float* W  = (const float*)d_in[1];
    const float* b  = (const float*)d_in[2];
    const float* Wg = (const float*)d_in[3];
    const float* bg = (const float*)d_in[4];
    float* out = (float*)d_out;

    cudaFuncSetAttribute(moe_gemm_mma, cudaFuncAttributeMaxDynamicSharedMemorySize, GEMM_SMEM);

    prep_gate_kernel<<<PW_BLOCKS + GT_BLOCKS, GT_TOK>>>(x, W, Wg, bg);
    dim3 grid(NTOK / BM, NEXP, DIM / BN);   // m fastest (R12 config)
    moe_gemm_mma<<<grid, 256, GEMM_SMEM>>>(b);
    combine_kernel<<<8192, 256>>>(out);
}

// round 16
// speedup vs baseline: 1.0632x; 1.0147x over previous
#include <cuda_runtime.h>
#include <cuda_bf16.h>
#include <cuda_fp16.h>
#include <cstdint>

#define NTOK 65536
#define DIM  512
#define NEXP 8

// GEMM tile: BM=128 x BN=128, BK=64, 3-stage cp.async, fp16 1-pass,
// 8 warps (2m x 4n), warp tile 64x32.  (R12 configuration)
#define BM 128
#define BN 128
#define BK 64
#define KSTEPS (DIM / BK)          // 8
#define STAGES 3
#define ROWB 144                   // bytes per smem tile row (64 fp16 + 16B pad)
#define TILE_B (128 * ROWB)        // 18432 : one tile (A or B)
#define BUF_B  (2 * TILE_B)        // 36864 : one stage (A + B)
#define OFF_TOK   0
#define OFF_DST   512
#define OFF_WT    1024
#define OFF_BIAS  1536
#define OFF_TILES 2048
#define GEMM_SMEM (OFF_TILES + STAGES * BUF_B)   // 112640 -> 2 CTAs/SM

// gate v5: 256 threads = 256 tokens, cp.async double-buffered x staging
#define GT_TOK 256
#define GCH 32                     // chunks of 16 floats (4 float4) along DIM

// ---------------- device scratch ----------------
__device__ unsigned  g_cnt[NEXP];
__device__ int       g_tok[NEXP * NTOK];
__device__ float     g_wt [NEXP * NTOK];
__device__ __half    g_xh[(size_t)NTOK * DIM];
__device__ __half    g_wh[(size_t)NEXP * DIM * DIM];
__device__ __half    g_scrh[(size_t)2 * NTOK * DIM];   // fp16 contributions

// ---------------- helpers ----------------
__device__ __forceinline__ uint32_t pkh(__half a, __half b) {
    return (uint32_t)__half_as_ushort(a) | ((uint32_t)__half_as_ushort(b) << 16);
}
__device__ __forceinline__ uint32_t smem_u32(const void* p) {
    return (uint32_t)__cvta_generic_to_shared(p);
}
__device__ __forceinline__ void cpasync16(uint32_t dst, const void* src) {
    asm volatile("cp.async.cg.shared.global [%0], [%1], 16;\n" :: "r"(dst), "l"(src));
}
__device__ __forceinline__ void cp_commit() { asm volatile("cp.async.commit_group;\n" ::: "memory"); }
__device__ __forceinline__ void cp_wait1()  { asm volatile("cp.async.wait_group 1;\n" ::: "memory"); }
__device__ __forceinline__ void cp_wait0()  { asm volatile("cp.async.wait_group 0;\n" ::: "memory"); }

__device__ __forceinline__ void ldmx4(uint32_t* r, uint32_t addr) {
    asm volatile("ldmatrix.sync.aligned.m8n8.x4.shared.b16 {%0,%1,%2,%3}, [%4];\n"
                 : "=r"(r[0]), "=r"(r[1]), "=r"(r[2]), "=r"(r[3]) : "r"(addr));
}
__device__ __forceinline__ void mma16816h(float* c, const uint32_t* a, uint32_t b0, uint32_t b1) {
    asm volatile("mma.sync.aligned.m16n8k16.row.col.f32.f16.f16.f32 "
                 "{%0,%1,%2,%3}, {%4,%5,%6,%7}, {%8,%9}, {%0,%1,%2,%3};\n"
                 : "+f"(c[0]), "+f"(c[1]), "+f"(c[2]), "+f"(c[3])
                 : "r"(a[0]), "r"(a[1]), "r"(a[2]), "r"(a[3]), "r"(b0), "r"(b1));
}

// ---------------- kernel 1: W -> fp16 (+ counter reset folded in) ----------------
__global__ void prepw_kernel(const float* __restrict__ W) {
    if (blockIdx.x == 0 && threadIdx.x < NEXP) g_cnt[threadIdx.x] = 0;
    int idx = blockIdx.x * blockDim.x + threadIdx.x;
    float4 v = reinterpret_cast<const float4*>(W)[idx];
    uint2 u;
    u.x = pkh(__float2half_rn(v.x), __float2half_rn(v.y));
    u.y = pkh(__float2half_rn(v.z), __float2half_rn(v.w));
    reinterpret_cast<uint2*>(g_wh)[idx] = u;
}

// ---------------- kernel 2: gate v5 — cp.async double-buffered, thread-per-token ----------------
// 256 threads = 256 tokens; x staged in 32 chunks of 16 floats via cp.async
// into 2 ping-pong buffers; Wg reads are warp-broadcasts; fp16 conversion
// reads back from smem.
__global__ __launch_bounds__(GT_TOK, 3) void gate_kernel(const float* __restrict__ x,
                                                         const float* __restrict__ Wg,
                                                         const float* __restrict__ bg) {
    __shared__ float4 sWg4[NEXP * 128];            // 16 KB
    __shared__ float4 xs4[2][GT_TOK * 5];          // 2 x 20 KB (4 float4 + 1 pad per token)
    const int tid = threadIdx.x;
    const int t0  = blockIdx.x * GT_TOK;

    for (int i = tid; i < NEXP * 128; i += GT_TOK)
        sWg4[i] = reinterpret_cast<const float4*>(Wg)[i];

    // loader geometry: idx = tid + j*256 -> row = (tid>>2)+64j, k4 = tid&3
    const int lrow = tid >> 2;
    const int lk4  = tid & 3;
    const float* xr[4];
#pragma unroll
    for (int j = 0; j < 4; j++)
        xr[j] = x + (size_t)(t0 + lrow + 64 * j) * DIM + lk4 * 4;
    uint32_t xdst[2][4];
#pragma unroll
    for (int bufi = 0; bufi < 2; bufi++)
#pragma unroll
        for (int j = 0; j < 4; j++)
            xdst[bufi][j] = smem_u32(&xs4[bufi][(lrow + 64 * j) * 5 + lk4]);

    float acc[NEXP];
#pragma unroll
    for (int e = 0; e < NEXP; e++) acc[e] = 0.f;

    // prologue: chunk 0 in flight
#pragma unroll
    for (int j = 0; j < 4; j++) cpasync16(xdst[0][j], xr[j]);
    cp_commit();

    int buf = 0;
    for (int c = 0; c < GCH; c++) {
        if (c + 1 < GCH) {
#pragma unroll
            for (int j = 0; j < 4; j++) cpasync16(xdst[buf ^ 1][j], xr[j] + (c + 1) * 16);
            cp_commit();
            cp_wait1();
        } else {
            cp_wait0();
        }
        __syncthreads();

        // expert dots (Wg = broadcast)
#pragma unroll
        for (int k4 = 0; k4 < 4; k4++) {
            const float4 xv = xs4[buf][tid * 5 + k4];
#pragma unroll
            for (int e = 0; e < NEXP; e++) {
                const float4 wv = sWg4[e * 128 + c * 4 + k4];
                acc[e] += xv.x * wv.x;
                acc[e] += xv.y * wv.y;
                acc[e] += xv.z * wv.z;
                acc[e] += xv.w * wv.w;
            }
        }
        // fp16 conversion from smem -> g_xh
#pragma unroll
        for (int j = 0; j < 4; j++) {
            const float4 v = xs4[buf][(lrow + 64 * j) * 5 + lk4];
            uint2 u;
            u.x = pkh(__float2half_rn(v.x), __float2half_rn(v.y));
            u.y = pkh(__float2half_rn(v.z), __float2half_rn(v.w));
            reinterpret_cast<uint2*>(g_xh)[(size_t)(t0 + lrow + 64 * j) * 128 + c * 4 + lk4] = u;
        }
        __syncthreads();
        buf ^= 1;
    }

    // top-2, softmax, bucket append
    const int t = t0 + tid;
    float v[NEXP];
#pragma unroll
    for (int e = 0; e < NEXP; e++) v[e] = acc[e] + bg[e];
    int e0 = 0;
#pragma unroll
    for (int e = 1; e < NEXP; e++) if (v[e] > v[e0]) e0 = e;   // ties: lower index
    int e1 = (e0 == 0) ? 1 : 0;
#pragma unroll
    for (int e = 0; e < NEXP; e++) if (e != e0 && v[e] > v[e1]) e1 = e;
    float d  = expf(v[e1] - v[e0]);
    float w0 = 1.f / (1.f + d);
    float w1 = 1.f - w0;

    unsigned p0 = atomicAdd(&g_cnt[e0], 1u);
    g_tok[e0 * NTOK + p0] = t;
    g_wt [e0 * NTOK + p0] = w0;
    unsigned p1 = atomicAdd(&g_cnt[e1], 1u);
    g_tok[e1 * NTOK + p1] = t | (1 << 16);
    g_wt [e1 * NTOK + p1] = w1;
}

// ---------------- kernel 3: grouped expert GEMM, fp16, 8 warps x (64x32), BK=64 ----------------
__global__ __launch_bounds__(256, 2) void moe_gemm_mma(const float* __restrict__ bias) {
    extern __shared__ char smem[];
    const int e = blockIdx.y;
    const unsigned cnt = g_cnt[e];
    const int m0 = blockIdx.x * BM;
    if ((unsigned)m0 >= cnt) return;
    const int valid = min(BM, (int)(cnt - m0));
    const int n0 = blockIdx.z * BN;

    const int tid  = threadIdx.x;
    const int lane = tid & 31, wid = tid >> 5;
    const int warp_m = wid & 1, warp_n = wid >> 1;   // 2m x 4n
    const uint32_t sb = smem_u32(smem);

    int*   s_tok  = reinterpret_cast<int*>(smem + OFF_TOK);
    int*   s_dst  = reinterpret_cast<int*>(smem + OFF_DST);
    float* s_wt   = reinterpret_cast<float*>(smem + OFF_WT);
    float* s_bias = reinterpret_cast<float*>(smem + OFF_BIAS);

    if (tid < 128) {
        int raw = 0; float w = 0.f;
        if (tid < valid) { raw = g_tok[e * NTOK + m0 + tid]; w = g_wt[e * NTOK + m0 + tid]; }
        int t = raw & 0xFFFF;
        s_tok[tid] = t;
        s_dst[tid] = (raw >> 16) * NTOK + t;
        s_wt [tid] = w;
        s_bias[tid] = bias[e * DIM + n0 + tid];
    }
    __syncthreads();

    // ---- loader: each thread owns rows r0+32j (j<4) of A and B, one 16B chunk col
    const int r0 = tid >> 3;          // 0..31
    const int cc = tid & 7;           // 16B chunk within 128B row
    const char* srcA[4];
#pragma unroll
    for (int j = 0; j < 4; j++)
        srcA[j] = reinterpret_cast<const char*>(g_xh + (size_t)s_tok[r0 + 32 * j] * DIM + cc * 8);
    const char* srcB = reinterpret_cast<const char*>(
        g_wh + (size_t)e * DIM * DIM + (size_t)(n0 + r0) * DIM + cc * 8);
    const uint32_t dstA = sb + OFF_TILES + r0 * ROWB + cc * 16;
    const uint32_t dstB = dstA + TILE_B;

    // ---- ldmatrix base addresses (buf 0, k16 = 0); add bufOff + k16*32 at use
    const int aRow = ((lane >> 3) & 1) * 8 + (lane & 7);
    const int aCol = ((lane >> 4) & 1) * 8;
    const int bRow = ((lane >> 4) & 1) * 8 + (lane & 7);
    const int bCol = ((lane >> 3) & 1) * 8;
    uint32_t aAddr[4], bAddr[2];
#pragma unroll
    for (int mt = 0; mt < 4; mt++)
        aAddr[mt] = sb + OFF_TILES + (warp_m * 64 + mt * 16 + aRow) * ROWB + aCol * 2;
#pragma unroll
    for (int pr = 0; pr < 2; pr++)
        bAddr[pr] = sb + OFF_TILES + TILE_B + (warp_n * 32 + pr * 16 + bRow) * ROWB + bCol * 2;

    float acc[4][4][4];
#pragma unroll
    for (int a = 0; a < 4; a++)
#pragma unroll
        for (int b2 = 0; b2 < 4; b2++)
#pragma unroll
            for (int c = 0; c < 4; c++) acc[a][b2][c] = 0.f;

    // ---- prologue: 2 stages in flight
#pragma unroll
    for (int ks = 0; ks < 2; ks++) {
        const uint32_t bo = ks * BUF_B;
        const int off = ks * (BK * 2);      // bytes along K
#pragma unroll
        for (int j = 0; j < 4; j++) cpasync16(dstA + bo + j * 32 * ROWB, srcA[j] + off);
#pragma unroll
        for (int j = 0; j < 4; j++) cpasync16(dstB + bo + j * 32 * ROWB, srcB + off + j * 32 * (DIM * 2));
        cp_commit();
    }

    // ---- mainloop: one barrier per 64-K stage (8 total)
    for (int ks = 0; ks < KSTEPS; ks++) {
        cp_wait1();
        __syncthreads();
        if (ks + 2 < KSTEPS) {
            const uint32_t bo = ((ks + 2) % STAGES) * BUF_B;
            const int off = (ks + 2) * (BK * 2);
#pragma unroll
            for (int j = 0; j < 4; j++) cpasync16(dstA + bo + j * 32 * ROWB, srcA[j] + off);
#pragma unroll
            for (int j = 0; j < 4; j++) cpasync16(dstB + bo + j * 32 * ROWB, srcB + off + j * 32 * (DIM * 2));
        }
        cp_commit();

        const uint32_t bufOff = (ks % STAGES) * BUF_B;
#pragma unroll
        for (int k16 = 0; k16 < 4; k16++) {
            const uint32_t ko = bufOff + k16 * 32;
            uint32_t ah[4][4];
#pragma unroll
            for (int mt = 0; mt < 4; mt++) ldmx4(ah[mt], aAddr[mt] + ko);
#pragma unroll
            for (int pr = 0; pr < 2; pr++) {
                uint32_t bh[4];
                ldmx4(bh, bAddr[pr] + ko);
                const int nt = pr * 2;
#pragma unroll
                for (int mt = 0; mt < 4; mt++) {
                    mma16816h(acc[mt][nt],     ah[mt], bh[0], bh[1]);
                    mma16816h(acc[mt][nt + 1], ah[mt], bh[2], bh[3]);
                }
            }
        }
    }

    // ---- epilogue: scr = half( w * (acc + bias) )  (deterministic slot)
    const int g  = lane >> 2;
    const int tg = lane & 3;
#pragma unroll
    for (int mt = 0; mt < 4; mt++) {
        const int rr0 = warp_m * 64 + mt * 16 + g;
        const int rr1 = rr0 + 8;
        const bool ok0 = rr0 < valid, ok1 = rr1 < valid;
        const float w0 = s_wt[rr0], w1 = s_wt[rr1];
        const size_t d0 = (size_t)s_dst[rr0] * DIM;
        const size_t d1 = (size_t)s_dst[rr1] * DIM;
#pragma unroll
        for (int nt = 0; nt < 4; nt++) {
            const int cloc = warp_n * 32 + nt * 8 + tg * 2;
            const int col  = n0 + cloc;
            const float b0v = s_bias[cloc], b1v = s_bias[cloc + 1];
            if (ok0) {
                __half2 h = __floats2half2_rn(w0 * (acc[mt][nt][0] + b0v),
                                              w0 * (acc[mt][nt][1] + b1v));
                *reinterpret_cast<__half2*>(g_scrh + d0 + col) = h;
            }
            if (ok1) {
                __half2 h = __floats2half2_rn(w1 * (acc[mt][nt][2] + b0v),
                                              w1 * (acc[mt][nt][3] + b1v));
                *reinterpret_cast<__half2*>(g_scrh + d1 + col) = h;
            }
        }
    }
}

// ---------------- kernel 4: combine (fp16 scr -> fp32 out) ----------------
__global__ void combine_kernel(float* __restrict__ out) {
    const uint4* s = reinterpret_cast<const uint4*>(g_scrh);   // 8 halves per uint4
    float4* o = reinterpret_cast<float4*>(out);
    const int total = NTOK * (DIM / 8);
    for (int i = blockIdx.x * blockDim.x + threadIdx.x; i < total; i += gridDim.x * blockDim.x) {
        uint4 a = s[i];
        uint4 b = s[i + total];
        const __half2* ah = reinterpret_cast<const __half2*>(&a);
        const __half2* bh = reinterpret_cast<const __half2*>(&b);
        float4 o0, o1;
        float2 p0 = __half22float2(ah[0]), q0 = __half22float2(bh[0]);
        float2 p1 = __half22float2(ah[1]), q1 = __half22float2(bh[1]);
        float2 p2 = __half22float2(ah[2]), q2 = __half22float2(bh[2]);
        float2 p3 = __half22float2(ah[3]), q3 = __half22float2(bh[3]);
        o0.x = p0.x + q0.x; o0.y = p0.y + q0.y;
        o0.z = p1.x + q1.x; o0.w = p1.y + q1.y;
        o1.x = p2.x + q2.x; o1.y = p2.y + q2.y;
        o1.z = p3.x + q3.x; o1.w = p3.y + q3.y;
        o[i * 2]     = o0;
        o[i * 2 + 1] = o1;
    }
}

// ---------------- launch ----------------
extern "C" void kernel_launch(void* const* d_in, const int* in_sizes, int n_in,
                              void* d_out, int out_size) {
    const float* x  = (const float*)d_in[0];
    const float* W  = (const float*)d_in[1];
    const float* b  = (const float*)d_in[2];
    const float* Wg = (const float*)d_in[3];
    const float* bg = (const float*)d_in[4];
    float* out = (float*)d_out;

    cudaFuncSetAttribute(moe_gemm_mma, cudaFuncAttributeMaxDynamicSharedMemorySize, GEMM_SMEM);

    prepw_kernel<<<(NEXP * DIM * DIM / 4) / 256, 256>>>(W);
    gate_kernel<<<NTOK / GT_TOK, GT_TOK>>>(x, Wg, bg);
    dim3 grid(NTOK / BM, NEXP, DIM / BN);   // m fastest (R12 config)
    moe_gemm_mma<<<grid, 256, GEMM_SMEM>>>(b);
    combine_kernel<<<8192, 256>>>(out);
}

// round 17
// speedup vs baseline: 1.0899x; 1.0251x over previous
#include <cuda_runtime.h>
#include <cuda_bf16.h>
#include <cuda_fp16.h>
#include <cstdint>

#define NTOK 65536
#define DIM  512
#define NEXP 8

// GEMM tile: BM=128 x BN=128, BK=64, 3-stage cp.async, fp16 1-pass,
// 8 warps (2m x 4n), warp tile 64x32.  (R12 configuration)
#define BM 128
#define BN 128
#define BK 64
#define KSTEPS (DIM / BK)          // 8
#define STAGES 3
#define ROWB 144                   // bytes per smem tile row (64 fp16 + 16B pad)
#define TILE_B (128 * ROWB)        // 18432 : one tile (A or B)
#define BUF_B  (2 * TILE_B)        // 36864 : one stage (A + B)
#define OFF_TOK   0
#define OFF_DST   512
#define OFF_WT    1024
#define OFF_BIAS  1536
#define OFF_TILES 2048
#define GEMM_SMEM (OFF_TILES + STAGES * BUF_B)   // 112640 -> 2 CTAs/SM

// gate v6: 256 threads = 256 tokens; per-warp private staging (no block barriers)
#define GT_TOK 256
#define GCH 32                     // chunks of 16 floats per token

// ---------------- device scratch ----------------
__device__ unsigned  g_cnt[NEXP];
__device__ int       g_tok[NEXP * NTOK];
__device__ float     g_wt [NEXP * NTOK];
__device__ __half    g_xh[(size_t)NTOK * DIM];
__device__ __half    g_wh[(size_t)NEXP * DIM * DIM];
__device__ __half    g_scrh[(size_t)2 * NTOK * DIM];   // fp16 contributions

// ---------------- helpers ----------------
__device__ __forceinline__ uint32_t pkh(__half a, __half b) {
    return (uint32_t)__half_as_ushort(a) | ((uint32_t)__half_as_ushort(b) << 16);
}
__device__ __forceinline__ uint32_t smem_u32(const void* p) {
    return (uint32_t)__cvta_generic_to_shared(p);
}
__device__ __forceinline__ void cpasync16(uint32_t dst, const void* src) {
    asm volatile("cp.async.cg.shared.global [%0], [%1], 16;\n" :: "r"(dst), "l"(src));
}
__device__ __forceinline__ void cp_commit() { asm volatile("cp.async.commit_group;\n" ::: "memory"); }
__device__ __forceinline__ void cp_wait1()  { asm volatile("cp.async.wait_group 1;\n" ::: "memory"); }
__device__ __forceinline__ void cp_wait0()  { asm volatile("cp.async.wait_group 0;\n" ::: "memory"); }

__device__ __forceinline__ void ldmx4(uint32_t* r, uint32_t addr) {
    asm volatile("ldmatrix.sync.aligned.m8n8.x4.shared.b16 {%0,%1,%2,%3}, [%4];\n"
                 : "=r"(r[0]), "=r"(r[1]), "=r"(r[2]), "=r"(r[3]) : "r"(addr));
}
__device__ __forceinline__ void mma16816h(float* c, const uint32_t* a, uint32_t b0, uint32_t b1) {
    asm volatile("mma.sync.aligned.m16n8k16.row.col.f32.f16.f16.f32 "
                 "{%0,%1,%2,%3}, {%4,%5,%6,%7}, {%8,%9}, {%0,%1,%2,%3};\n"
                 : "+f"(c[0]), "+f"(c[1]), "+f"(c[2]), "+f"(c[3])
                 : "r"(a[0]), "r"(a[1]), "r"(a[2]), "r"(a[3]), "r"(b0), "r"(b1));
}

// ---------------- kernel 1: W -> fp16 (+ counter reset folded in) ----------------
__global__ void prepw_kernel(const float* __restrict__ W) {
    if (blockIdx.x == 0 && threadIdx.x < NEXP) g_cnt[threadIdx.x] = 0;
    int idx = blockIdx.x * blockDim.x + threadIdx.x;
    float4 v = reinterpret_cast<const float4*>(W)[idx];
    uint2 u;
    u.x = pkh(__float2half_rn(v.x), __float2half_rn(v.y));
    u.y = pkh(__float2half_rn(v.z), __float2half_rn(v.w));
    reinterpret_cast<uint2*>(g_wh)[idx] = u;
}

// ---------------- kernel 2: gate v6 — per-warp staging, thread-per-token ----------------
// Each warp owns 32 tokens + a private 2-buffer smem slice. No block barriers
// in the mainloop: each lane waits its own cp.async groups; __syncwarp makes
// the whole chunk visible warp-wide.
__global__ __launch_bounds__(GT_TOK, 3) void gate_kernel(const float* __restrict__ x,
                                                         const float* __restrict__ Wg,
                                                         const float* __restrict__ bg) {
    __shared__ float4 sWg4[NEXP * 128];               // 16 KB
    __shared__ float4 xs4[8][2][32 * 5];              // 8 warps x 2 bufs x (4 f4 + pad)/token = 40 KB
    const int tid  = threadIdx.x;
    const int wid  = tid >> 5, lane = tid & 31;
    const int t0w  = blockIdx.x * GT_TOK + wid * 32;  // this warp's first token

    for (int i = tid; i < NEXP * 128; i += GT_TOK)
        sWg4[i] = reinterpret_cast<const float4*>(Wg)[i];
    __syncthreads();   // only block barrier: sWg ready

    // loader geometry: idx = lane + 32j (j<4) -> row = idx>>2 (0..31), k4 = idx&3
    const float* xr[4];
    uint32_t xdst[2][4];
#pragma unroll
    for (int j = 0; j < 4; j++) {
        const int idx = lane + 32 * j;
        const int row = idx >> 2, k4 = idx & 3;
        xr[j] = x + (size_t)(t0w + row) * DIM + k4 * 4;
#pragma unroll
        for (int bufi = 0; bufi < 2; bufi++)
            xdst[bufi][j] = smem_u32(&xs4[wid][bufi][row * 5 + k4]);
    }

    float acc[NEXP];
#pragma unroll
    for (int e = 0; e < NEXP; e++) acc[e] = 0.f;

#pragma unroll
    for (int j = 0; j < 4; j++) cpasync16(xdst[0][j], xr[j]);
    cp_commit();

    int buf = 0;
    for (int c = 0; c < GCH; c++) {
        if (c + 1 < GCH) {
#pragma unroll
            for (int j = 0; j < 4; j++) cpasync16(xdst[buf ^ 1][j], xr[j] + (c + 1) * 16);
            cp_commit();
            cp_wait1();
        } else {
            cp_wait0();
        }
        __syncwarp();

        // expert dots for my token (Wg = broadcast)
#pragma unroll
        for (int k4 = 0; k4 < 4; k4++) {
            const float4 xv = xs4[wid][buf][lane * 5 + k4];
#pragma unroll
            for (int e = 0; e < NEXP; e++) {
                const float4 wv = sWg4[e * 128 + c * 4 + k4];
                acc[e] += xv.x * wv.x;
                acc[e] += xv.y * wv.y;
                acc[e] += xv.z * wv.z;
                acc[e] += xv.w * wv.w;
            }
        }
        // fp16 writeback of this chunk
#pragma unroll
        for (int j = 0; j < 4; j++) {
            const int idx = lane + 32 * j;
            const int row = idx >> 2, k4 = idx & 3;
            const float4 v = xs4[wid][buf][row * 5 + k4];
            uint2 u;
            u.x = pkh(__float2half_rn(v.x), __float2half_rn(v.y));
            u.y = pkh(__float2half_rn(v.z), __float2half_rn(v.w));
            reinterpret_cast<uint2*>(g_xh)[(size_t)(t0w + row) * 128 + c * 4 + k4] = u;
        }
        __syncwarp();
        buf ^= 1;
    }

    // top-2, softmax, bucket append
    const int t = t0w + lane;
    float v[NEXP];
#pragma unroll
    for (int e = 0; e < NEXP; e++) v[e] = acc[e] + bg[e];
    int e0 = 0;
#pragma unroll
    for (int e = 1; e < NEXP; e++) if (v[e] > v[e0]) e0 = e;   // ties: lower index
    int e1 = (e0 == 0) ? 1 : 0;
#pragma unroll
    for (int e = 0; e < NEXP; e++) if (e != e0 && v[e] > v[e1]) e1 = e;
    float d  = expf(v[e1] - v[e0]);
    float w0 = 1.f / (1.f + d);
    float w1 = 1.f - w0;

    unsigned p0 = atomicAdd(&g_cnt[e0], 1u);
    g_tok[e0 * NTOK + p0] = t;
    g_wt [e0 * NTOK + p0] = w0;
    unsigned p1 = atomicAdd(&g_cnt[e1], 1u);
    g_tok[e1 * NTOK + p1] = t | (1 << 16);
    g_wt [e1 * NTOK + p1] = w1;
}

// ---------------- kernel 3: grouped expert GEMM, fp16, 8 warps x (64x32), BK=64 ----------------
__global__ __launch_bounds__(256, 2) void moe_gemm_mma(const float* __restrict__ bias) {
    extern __shared__ char smem[];
    const int e = blockIdx.y;
    const unsigned cnt = g_cnt[e];
    const int m0 = blockIdx.x * BM;
    if ((unsigned)m0 >= cnt) return;
    const int valid = min(BM, (int)(cnt - m0));
    const int n0 = blockIdx.z * BN;

    const int tid  = threadIdx.x;
    const int lane = tid & 31, wid = tid >> 5;
    const int warp_m = wid & 1, warp_n = wid >> 1;   // 2m x 4n
    const uint32_t sb = smem_u32(smem);

    int*   s_tok  = reinterpret_cast<int*>(smem + OFF_TOK);
    int*   s_dst  = reinterpret_cast<int*>(smem + OFF_DST);
    float* s_wt   = reinterpret_cast<float*>(smem + OFF_WT);
    float* s_bias = reinterpret_cast<float*>(smem + OFF_BIAS);

    if (tid < 128) {
        int raw = 0; float w = 0.f;
        if (tid < valid) { raw = g_tok[e * NTOK + m0 + tid]; w = g_wt[e * NTOK + m0 + tid]; }
        int t = raw & 0xFFFF;
        s_tok[tid] = t;
        s_dst[tid] = (raw >> 16) * NTOK + t;
        s_wt [tid] = w;
        s_bias[tid] = bias[e * DIM + n0 + tid];
    }
    __syncthreads();

    // ---- loader: each thread owns rows r0+32j (j<4) of A and B, one 16B chunk col
    const int r0 = tid >> 3;          // 0..31
    const int cc = tid & 7;           // 16B chunk within 128B row
    const char* srcA[4];
#pragma unroll
    for (int j = 0; j < 4; j++)
        srcA[j] = reinterpret_cast<const char*>(g_xh + (size_t)s_tok[r0 + 32 * j] * DIM + cc * 8);
    const char* srcB = reinterpret_cast<const char*>(
        g_wh + (size_t)e * DIM * DIM + (size_t)(n0 + r0) * DIM + cc * 8);
    const uint32_t dstA = sb + OFF_TILES + r0 * ROWB + cc * 16;
    const uint32_t dstB = dstA + TILE_B;

    // ---- ldmatrix base addresses (buf 0, k16 = 0); add bufOff + k16*32 at use
    const int aRow = ((lane >> 3) & 1) * 8 + (lane & 7);
    const int aCol = ((lane >> 4) & 1) * 8;
    const int bRow = ((lane >> 4) & 1) * 8 + (lane & 7);
    const int bCol = ((lane >> 3) & 1) * 8;
    uint32_t aAddr[4], bAddr[2];
#pragma unroll
    for (int mt = 0; mt < 4; mt++)
        aAddr[mt] = sb + OFF_TILES + (warp_m * 64 + mt * 16 + aRow) * ROWB + aCol * 2;
#pragma unroll
    for (int pr = 0; pr < 2; pr++)
        bAddr[pr] = sb + OFF_TILES + TILE_B + (warp_n * 32 + pr * 16 + bRow) * ROWB + bCol * 2;

    float acc[4][4][4];
#pragma unroll
    for (int a = 0; a < 4; a++)
#pragma unroll
        for (int b2 = 0; b2 < 4; b2++)
#pragma unroll
            for (int c = 0; c < 4; c++) acc[a][b2][c] = 0.f;

    // ---- prologue: 2 stages in flight
#pragma unroll
    for (int ks = 0; ks < 2; ks++) {
        const uint32_t bo = ks * BUF_B;
        const int off = ks * (BK * 2);      // bytes along K
#pragma unroll
        for (int j = 0; j < 4; j++) cpasync16(dstA + bo + j * 32 * ROWB, srcA[j] + off);
#pragma unroll
        for (int j = 0; j < 4; j++) cpasync16(dstB + bo + j * 32 * ROWB, srcB + off + j * 32 * (DIM * 2));
        cp_commit();
    }

    // ---- mainloop: one barrier per 64-K stage (8 total)
    for (int ks = 0; ks < KSTEPS; ks++) {
        cp_wait1();
        __syncthreads();
        if (ks + 2 < KSTEPS) {
            const uint32_t bo = ((ks + 2) % STAGES) * BUF_B;
            const int off = (ks + 2) * (BK * 2);
#pragma unroll
            for (int j = 0; j < 4; j++) cpasync16(dstA + bo + j * 32 * ROWB, srcA[j] + off);
#pragma unroll
            for (int j = 0; j < 4; j++) cpasync16(dstB + bo + j * 32 * ROWB, srcB + off + j * 32 * (DIM * 2));
        }
        cp_commit();

        const uint32_t bufOff = (ks % STAGES) * BUF_B;
#pragma unroll
        for (int k16 = 0; k16 < 4; k16++) {
            const uint32_t ko = bufOff + k16 * 32;
            uint32_t ah[4][4];
#pragma unroll
            for (int mt = 0; mt < 4; mt++) ldmx4(ah[mt], aAddr[mt] + ko);
#pragma unroll
            for (int pr = 0; pr < 2; pr++) {
                uint32_t bh[4];
                ldmx4(bh, bAddr[pr] + ko);
                const int nt = pr * 2;
#pragma unroll
                for (int mt = 0; mt < 4; mt++) {
                    mma16816h(acc[mt][nt],     ah[mt], bh[0], bh[1]);
                    mma16816h(acc[mt][nt + 1], ah[mt], bh[2], bh[3]);
                }
            }
        }
    }

    // ---- epilogue: scr = half( w * (acc + bias) )  (deterministic slot)
    const int g  = lane >> 2;
    const int tg = lane & 3;
#pragma unroll
    for (int mt = 0; mt < 4; mt++) {
        const int rr0 = warp_m * 64 + mt * 16 + g;
        const int rr1 = rr0 + 8;
        const bool ok0 = rr0 < valid, ok1 = rr1 < valid;
        const float w0 = s_wt[rr0], w1 = s_wt[rr1];
        const size_t d0 = (size_t)s_dst[rr0] * DIM;
        const size_t d1 = (size_t)s_dst[rr1] * DIM;
#pragma unroll
        for (int nt = 0; nt < 4; nt++) {
            const int cloc = warp_n * 32 + nt * 8 + tg * 2;
            const int col  = n0 + cloc;
            const float b0v = s_bias[cloc], b1v = s_bias[cloc + 1];
            if (ok0) {
                __half2 h = __floats2half2_rn(w0 * (acc[mt][nt][0] + b0v),
                                              w0 * (acc[mt][nt][1] + b1v));
                *reinterpret_cast<__half2*>(g_scrh + d0 + col) = h;
            }
            if (ok1) {
                __half2 h = __floats2half2_rn(w1 * (acc[mt][nt][2] + b0v),
                                              w1 * (acc[mt][nt][3] + b1v));
                *reinterpret_cast<__half2*>(g_scrh + d1 + col) = h;
            }
        }
    }
}

// ---------------- kernel 4: combine (fp16 scr -> fp32 out) ----------------
__global__ void combine_kernel(float* __restrict__ out) {
    const uint4* s = reinterpret_cast<const uint4*>(g_scrh);   // 8 halves per uint4
    float4* o = reinterpret_cast<float4*>(out);
    const int total = NTOK * (DIM / 8);
    for (int i = blockIdx.x * blockDim.x + threadIdx.x; i < total; i += gridDim.x * blockDim.x) {
        uint4 a = s[i];
        uint4 b = s[i + total];
        const __half2* ah = reinterpret_cast<const __half2*>(&a);
        const __half2* bh = reinterpret_cast<const __half2*>(&b);
        float4 o0, o1;
        float2 p0 = __half22float2(ah[0]), q0 = __half22float2(bh[0]);
        float2 p1 = __half22float2(ah[1]), q1 = __half22float2(bh[1]);
        float2 p2 = __half22float2(ah[2]), q2 = __half22float2(bh[2]);
        float2 p3 = __half22float2(ah[3]), q3 = __half22float2(bh[3]);
        o0.x = p0.x + q0.x; o0.y = p0.y + q0.y;
        o0.z = p1.x + q1.x; o0.w = p1.y + q1.y;
        o1.x = p2.x + q2.x; o1.y = p2.y + q2.y;
        o1.z = p3.x + q3.x; o1.w = p3.y + q3.y;
        o[i * 2]     = o0;
        o[i * 2 + 1] = o1;
    }
}

// ---------------- launch ----------------
extern "C" void kernel_launch(void* const* d_in, const int* in_sizes, int n_in,
                              void* d_out, int out_size) {
    const float* x  = (const float*)d_in[0];
    const float* W  = (const float*)d_in[1];
    const float* b  = (const float*)d_in[2];
    const float* Wg = (const float*)d_in[3];
    const float* bg = (const float*)d_in[4];
    float* out = (float*)d_out;

    cudaFuncSetAttribute(moe_gemm_mma, cudaFuncAttributeMaxDynamicSharedMemorySize, GEMM_SMEM);

    prepw_kernel<<<(NEXP * DIM * DIM / 4) / 256, 256>>>(W);
    gate_kernel<<<NTOK / GT_TOK, GT_TOK>>>(x, Wg, bg);
    dim3 grid(NTOK / BM, NEXP, DIM / BN);   // m fastest (R12 config)
    moe_gemm_mma<<<grid, 256, GEMM_SMEM>>>(b);
    combine_kernel<<<8192, 256>>>(out);
}